// round 12
// baseline (speedup 1.0000x reference)
#include <cuda_runtime.h>
#include <cuda_bf16.h>

#define N_NODES 100000
#define N_EDGES 1600000
#define IN_CH 8
#define HID_CH 64
#define OUT_CH 2

#define NB 444   // 148 SMs x 3 blocks — guaranteed co-resident
#define NT 256

// Scratch (allocation-free rule: __device__ globals).
__device__ __align__(32) float g_sum_x[N_NODES * IN_CH];
__device__ __align__(16) float g_cnt[N_NODES];
__device__ __align__(16) float g_p[N_NODES * OUT_CH];
__device__ __align__(16) float g_self[N_NODES * OUT_CH];
__device__ __align__(16) float g_sum_p[N_NODES * OUT_CH];

// Software grid barrier state. bar_count returns to 0 after each barrier;
// bar_gen increases monotonically (replay-safe, wrap harmless).
__device__ unsigned g_bar_count = 0;
__device__ volatile unsigned g_bar_gen = 0;

__device__ __forceinline__ void grid_barrier() {
    __syncthreads();
    if (threadIdx.x == 0) {
        __threadfence();                       // release prior writes/atomics
        unsigned gen = g_bar_gen;
        if (atomicAdd(&g_bar_count, 1u) == (unsigned)(gridDim.x - 1)) {
            g_bar_count = 0;
            __threadfence();
            g_bar_gen = gen + 1;               // release
        } else {
            while (g_bar_gen == gen) __nanosleep(64);
        }
        __threadfence();                       // acquire
    }
    __syncthreads();
}

__global__ __launch_bounds__(NT, 3)
void fused_kernel(const float* __restrict__ x,
                  const int* __restrict__ ei, int E, int N,
                  const float* __restrict__ W_l1,  // [64,8]
                  const float* __restrict__ b_l1,  // [64]
                  const float* __restrict__ W_r1,  // [64,8]
                  const float* __restrict__ W_l2,  // [2,64]
                  const float* __restrict__ b_l2,  // [2]
                  const float* __restrict__ W_r2,  // [2,64]
                  float* __restrict__ out) {
    __shared__ float sWl1[HID_CH * IN_CH];
    __shared__ float sWr1[HID_CH * IN_CH];
    __shared__ float sWl2[OUT_CH * HID_CH];
    __shared__ float sWr2[OUT_CH * HID_CH];
    __shared__ float sb1[HID_CH];
    __shared__ float sb2[OUT_CH];

    const int tid  = threadIdx.x;
    const int idx  = blockIdx.x * NT + tid;
    const int T    = gridDim.x * NT;           // total threads

    // ---- Phase 0: stage weights (inputs, no deps) + zero accumulators ----
    for (int i = tid; i < HID_CH * IN_CH; i += NT) {
        sWl1[i] = W_l1[i];
        sWr1[i] = W_r1[i];
    }
    for (int i = tid; i < OUT_CH * HID_CH; i += NT) {
        sWl2[i] = W_l2[i];
        sWr2[i] = W_r2[i];
    }
    if (tid < HID_CH) sb1[tid] = b_l1[tid];
    if (tid < OUT_CH) sb2[tid] = b_l2[tid];

    {
        const int n_sx = N_NODES * IN_CH / 4;   // 200000
        const int n_cn = N_NODES / 4;           //  25000
        const int n_sp = N_NODES * OUT_CH / 4;  //  50000
        const int tot  = n_sx + n_cn + n_sp;    // 275000
        float4 z = make_float4(0.f, 0.f, 0.f, 0.f);
        for (int i = idx; i < tot; i += T) {
            if (i < n_sx)            ((float4*)g_sum_x)[i] = z;
            else if (i < n_sx + n_cn) ((float4*)g_cnt)[i - n_sx] = z;
            else                      ((float4*)g_sum_p)[i - n_sx - n_cn] = z;
        }
    }
    grid_barrier();

    // ---- Phase 1: edge pass 1 (8 lanes/edge, 4 edges batched/iter) ----
    {
        const int t  = idx >> 3;
        const int ch = idx & 7;
        const int T8 = T >> 3;                  // edges per sweep
        for (int base = 0; base < E; base += 4 * T8) {
            int e[4]; bool v[4]; int src[4], dst[4]; float val[4];
#pragma unroll
            for (int k = 0; k < 4; k++) {
                e[k] = base + t + k * T8;
                v[k] = (e[k] < E);
                src[k] = 0; dst[k] = 0;
            }
#pragma unroll
            for (int k = 0; k < 4; k++)
                if (v[k]) { src[k] = ei[e[k]]; dst[k] = ei[E + e[k]]; }
#pragma unroll
            for (int k = 0; k < 4; k++) {
                val[k] = 0.0f;
                if (v[k]) val[k] = x[src[k] * IN_CH + ch];
            }
#pragma unroll
            for (int k = 0; k < 4; k++) {
                if (v[k]) {
                    atomicAdd(&g_sum_x[dst[k] * IN_CH + ch], val[k]);
                    if (ch == 0) atomicAdd(&g_cnt[dst[k]], 1.0f);
                }
            }
        }
    }
    grid_barrier();

    // ---- Phase 2: node: aggr -> lin1 -> ReLU -> p / self ----
    for (int i = idx; i < N; i += T) {
        float cnt = g_cnt[i];
        float inv = 1.0f / fmaxf(cnt, 1.0f);

        float aggr[IN_CH], xi[IN_CH];
        const float4* sx4 = (const float4*)&g_sum_x[i * IN_CH];
        float4 sa = sx4[0], sb = sx4[1];
        aggr[0] = sa.x * inv; aggr[1] = sa.y * inv; aggr[2] = sa.z * inv; aggr[3] = sa.w * inv;
        aggr[4] = sb.x * inv; aggr[5] = sb.y * inv; aggr[6] = sb.z * inv; aggr[7] = sb.w * inv;

        const float4* x4 = (const float4*)&x[i * IN_CH];
        float4 xa = x4[0], xb = x4[1];
        xi[0] = xa.x; xi[1] = xa.y; xi[2] = xa.z; xi[3] = xa.w;
        xi[4] = xb.x; xi[5] = xb.y; xi[6] = xb.z; xi[7] = xb.w;

        float p0 = 0.0f, p1 = 0.0f, s0 = 0.0f, s1 = 0.0f;
#pragma unroll
        for (int j = 0; j < HID_CH; j++) {
            float t = sb1[j];
#pragma unroll
            for (int k = 0; k < IN_CH; k++) {
                t = fmaf(aggr[k], sWl1[j * IN_CH + k], t);
                t = fmaf(xi[k],   sWr1[j * IN_CH + k], t);
            }
            float h = fmaxf(t, 0.0f);   // ReLU (dropout identity in eval)
            p0 = fmaf(h, sWl2[0 * HID_CH + j], p0);
            p1 = fmaf(h, sWl2[1 * HID_CH + j], p1);
            s0 = fmaf(h, sWr2[0 * HID_CH + j], s0);
            s1 = fmaf(h, sWr2[1 * HID_CH + j], s1);
        }

        g_p[i * 2 + 0] = p0;
        g_p[i * 2 + 1] = p1;
        g_self[i * 2 + 0] = s0 + sb2[0];
        g_self[i * 2 + 1] = s1 + sb2[1];
    }
    grid_barrier();

    // ---- Phase 3: edge pass 2 (2 lanes/edge, 4 edges batched/iter) ----
    {
        const int t  = idx >> 1;
        const int ch = idx & 1;
        const int T2 = T >> 1;
        for (int base = 0; base < E; base += 4 * T2) {
            int e[4]; bool v[4]; int src[4], dst[4]; float val[4];
#pragma unroll
            for (int k = 0; k < 4; k++) {
                e[k] = base + t + k * T2;
                v[k] = (e[k] < E);
                src[k] = 0; dst[k] = 0;
            }
#pragma unroll
            for (int k = 0; k < 4; k++)
                if (v[k]) { src[k] = ei[e[k]]; dst[k] = ei[E + e[k]]; }
#pragma unroll
            for (int k = 0; k < 4; k++) {
                val[k] = 0.0f;
                if (v[k]) val[k] = g_p[src[k] * 2 + ch];
            }
#pragma unroll
            for (int k = 0; k < 4; k++)
                if (v[k]) atomicAdd(&g_sum_p[dst[k] * 2 + ch], val[k]);
        }
    }
    grid_barrier();

    // ---- Phase 4: finalize ----
    for (int i = idx; i < N; i += T) {
        float inv = 1.0f / fmaxf(g_cnt[i], 1.0f);
        float2 sp = *(const float2*)&g_sum_p[i * 2];
        float2 se = *(const float2*)&g_self[i * 2];
        float2 o;
        o.x = sp.x * inv + se.x;
        o.y = sp.y * inv + se.y;
        *(float2*)&out[i * 2] = o;
    }
}

extern "C" void kernel_launch(void* const* d_in, const int* in_sizes, int n_in,
                              void* d_out, int out_size) {
    const float* x    = (const float*)d_in[0];
    const int*   ei   = (const int*)d_in[1];
    const float* W_l1 = (const float*)d_in[2];
    const float* b_l1 = (const float*)d_in[3];
    const float* W_r1 = (const float*)d_in[4];
    const float* W_l2 = (const float*)d_in[5];
    const float* b_l2 = (const float*)d_in[6];
    const float* W_r2 = (const float*)d_in[7];

    int E = in_sizes[1] / 2;
    int N = in_sizes[0] / IN_CH;

    fused_kernel<<<NB, NT>>>(x, ei, E, N, W_l1, b_l1, W_r1,
                             W_l2, b_l2, W_r2, (float*)d_out);
}